// round 3
// baseline (speedup 1.0000x reference)
#include <cuda_runtime.h>

#define BB 64
#define SS 256
#define TT 8
#define DD 256
#define E_EDGES 500000
#define M_CNT 2048
#define ROW_STRIDE (TT * DD)   // 2048 floats between consecutive (b,s) type rows
#define NEG_INF_F (-10000000000.0f)

#define LEMMA_BLOCKS 2048
#define TOTAL_BLOCKS (LEMMA_BLOCKS + M_CNT)

// Folded linear head: v = w1 @ w2 (D floats), c = b1.w2 + b2
__device__ float g_v[DD];
__device__ float g_c;

// ---------------------------------------------------------------------------
// Prep: fold the two linear layers. lemmas = (x_s*x_g) @ (w1@w2) + (b1@w2 + b2)
// ---------------------------------------------------------------------------
__global__ void prep_kernel(const float* __restrict__ w1,   // [D, D/2]
                            const float* __restrict__ b1,   // [D/2]
                            const float* __restrict__ w2,   // [D/2, 1]
                            const float* __restrict__ b2) { // [1]
    int d = threadIdx.x;  // 0..255
    float acc = 0.f;
    #pragma unroll 8
    for (int k = 0; k < DD / 2; k++)
        acc = fmaf(w1[d * (DD / 2) + k], w2[k], acc);
    g_v[d] = acc;
    if (d == 0) {
        float c = b2[0];
        for (int k = 0; k < DD / 2; k++)
            c = fmaf(b1[k], w2[k], c);
        g_c = c;
    }
}

__device__ __forceinline__ float warp_reduce_sum(float v) {
    #pragma unroll
    for (int off = 16; off > 0; off >>= 1)
        v += __shfl_xor_sync(0xFFFFFFFFu, v, off);
    return v;
}

// ---------------------------------------------------------------------------
// Lemma phase: warp per edge, grid-stride. lane covers d = lane*4 and
// 128 + lane*4 so each float4 load is a fully-coalesced 512B warp segment.
// ---------------------------------------------------------------------------
__device__ __forceinline__ void lemma_phase(
    const float* __restrict__ tok, const int* __restrict__ eidx,
    float* __restrict__ out, int block)
{
    const int lane   = threadIdx.x & 31;
    const int warp   = (block * blockDim.x + threadIdx.x) >> 5;
    const int nwarps = (LEMMA_BLOCKS * blockDim.x) >> 5;

    const float4* vv = reinterpret_cast<const float4*>(g_v);
    const float4 v0 = vv[lane];
    const float4 v1 = vv[32 + lane];
    const float  c  = g_c;

    for (int e = warp; e < E_EDGES; e += nwarps) {
        const int sidx = eidx[e];
        const int gidx = eidx[E_EDGES + e];

        const float4* rs = reinterpret_cast<const float4*>(tok + (size_t)sidx * ROW_STRIDE);
        const float4* rg = reinterpret_cast<const float4*>(tok + (size_t)gidx * ROW_STRIDE);

        const float4 s0 = rs[lane];
        const float4 s1 = rs[32 + lane];
        const float4 g0 = rg[lane];
        const float4 g1 = rg[32 + lane];

        float acc = 0.f;
        acc = fmaf(s0.x * g0.x, v0.x, acc);
        acc = fmaf(s0.y * g0.y, v0.y, acc);
        acc = fmaf(s0.z * g0.z, v0.z, acc);
        acc = fmaf(s0.w * g0.w, v0.w, acc);
        acc = fmaf(s1.x * g1.x, v1.x, acc);
        acc = fmaf(s1.y * g1.y, v1.y, acc);
        acc = fmaf(s1.z * g1.z, v1.z, acc);
        acc = fmaf(s1.w * g1.w, v1.w, acc);

        acc = warp_reduce_sum(acc);
        if (lane == 0) out[e] = acc + c;
    }
}

// ---------------------------------------------------------------------------
// lm phase: one block per m. Mask-repr row -> smem -> registers; warp per s.
// lm_preds[m,s] = dot(mask_reprs[m], type_reprs[bp[m], s]) or NEG_INF.
// Mask is int32 (harness materializes jnp.bool_ as int32).
// ---------------------------------------------------------------------------
__device__ __forceinline__ void lm_phase(
    const float* __restrict__ tok, const int* __restrict__ lm_idx,
    const int* __restrict__ bptr, const int* __restrict__ tpm,
    float* __restrict__ out, int m)
{
    __shared__ float q[DD];

    const int t = threadIdx.x;           // 256 threads
    const int row = lm_idx[m];           // in [0, B*S*T)
    q[t] = tok[(size_t)row * DD + t];
    __syncthreads();

    const int lane = t & 31;
    const int warp = t >> 5;             // 0..7

    const float4* qv = reinterpret_cast<const float4*>(q);
    const float4 q0 = qv[lane];
    const float4 q1 = qv[32 + lane];

    const int b = bptr[m];
    const float* base = tok + (size_t)b * SS * ROW_STRIDE;
    const int* mrow = tpm + (size_t)b * SS;
    float* orow = out + (size_t)E_EDGES + (size_t)m * SS;

    for (int s = warp; s < SS; s += 8) {
        const float4* cr = reinterpret_cast<const float4*>(base + (size_t)s * ROW_STRIDE);
        const float4 c0 = cr[lane];
        const float4 c1 = cr[32 + lane];

        float acc = 0.f;
        acc = fmaf(q0.x, c0.x, acc);
        acc = fmaf(q0.y, c0.y, acc);
        acc = fmaf(q0.z, c0.z, acc);
        acc = fmaf(q0.w, c0.w, acc);
        acc = fmaf(q1.x, c1.x, acc);
        acc = fmaf(q1.y, c1.y, acc);
        acc = fmaf(q1.z, c1.z, acc);
        acc = fmaf(q1.w, c1.w, acc);

        acc = warp_reduce_sum(acc);
        if (lane == 0)
            orow[s] = (mrow[s] != 0) ? acc : NEG_INF_F;
    }
}

// ---------------------------------------------------------------------------
// Fused kernel: blocks [0, LEMMA_BLOCKS) do the edge head; blocks
// [LEMMA_BLOCKS, LEMMA_BLOCKS+M) do lm_preds. The two phases are independent,
// so fusing them into one grid lets the ~50us lm phase hide inside the
// ~95us lemma phase instead of serializing after it.
// ---------------------------------------------------------------------------
__global__ void fused_kernel(const float* __restrict__ tok,
                             const int*   __restrict__ eidx,
                             const int*   __restrict__ lm_idx,
                             const int*   __restrict__ bptr,
                             const int*   __restrict__ tpm,
                             float*       __restrict__ out)
{
    const int blk = blockIdx.x;
    if (blk < LEMMA_BLOCKS) {
        lemma_phase(tok, eidx, out, blk);
    } else {
        lm_phase(tok, lm_idx, bptr, tpm, out, blk - LEMMA_BLOCKS);
    }
}

// ---------------------------------------------------------------------------
// Inputs (metadata order):
//  0 token_reprs f32 [B,S,T,D]
//  1 w1 f32 [D, D/2]
//  2 b1 f32 [D/2]
//  3 w2 f32 [D/2, 1]
//  4 b2 f32 [1]
//  5 edge_index i32 [2, E]
//  6 lm_indices i32 [M]
//  7 batch_pointers i32 [M]
//  8 tree_padding_mask (bool -> int32) [B, S]
// Output: float32, E lemmas followed by M*S lm_preds.
// ---------------------------------------------------------------------------
extern "C" void kernel_launch(void* const* d_in, const int* in_sizes, int n_in,
                              void* d_out, int out_size) {
    const float* tok  = (const float*)d_in[0];
    const float* w1   = (const float*)d_in[1];
    const float* b1   = (const float*)d_in[2];
    const float* w2   = (const float*)d_in[3];
    const float* b2   = (const float*)d_in[4];
    const int*   eidx = (const int*)d_in[5];
    const int*   lmi  = (const int*)d_in[6];
    const int*   bpt  = (const int*)d_in[7];
    const int*   tpm  = (const int*)d_in[8];
    float* out = (float*)d_out;

    prep_kernel<<<1, DD>>>(w1, b1, w2, b2);
    fused_kernel<<<TOTAL_BLOCKS, 256>>>(tok, eidx, lmi, bpt, tpm, out);
}